// round 1
// baseline (speedup 1.0000x reference)
#include <cuda_runtime.h>
#include <cstdint>

// ---------------- problem constants ----------------
#define D_      1024
#define E_      64
#define BATCH   8
#define SEQ     512
#define MAXTOK  4096          // worst case: no batch masked
#define MAXSLOT 8192          // MAXTOK * TOPK
#define TM      128
#define TN      64
#define TK      8

// ---------------- device scratch (no runtime allocs allowed) ----------------
__device__ int   g_keep[BATCH];
__device__ int   g_maskb[BATCH];
__device__ int   g_ntok;
__device__ int   g_fill;
__device__ int   g_eos[MAXSLOT];       // expert of slot
__device__ int   g_sorted[MAXSLOT];    // slot ids grouped by expert
__device__ int   g_ntiles;
__device__ int3  g_tiles[192];         // {expert, seg_start, cnt}
__device__ float g_logits[MAXTOK * E_];
__device__ float g_h1[(size_t)MAXSLOT * D_];   // 32 MB intermediate

// ---------------- helpers ----------------
__device__ __forceinline__ void fma_f32x2(unsigned long long& d,
                                          unsigned long long a,
                                          unsigned long long b) {
    asm("fma.rn.f32x2 %0, %1, %2, %0;" : "+l"(d) : "l"(a), "l"(b));
}

__device__ __forceinline__ float gelu_exact(float x) {
    return 0.5f * x * (1.0f + erff(x * 0.70710678118654752f));
}

__device__ __forceinline__ float blockReduce(float v, float* sh) {
    sh[threadIdx.x] = v;
    __syncthreads();
    for (int s = 128; s > 0; s >>= 1) {
        if ((int)threadIdx.x < s) sh[threadIdx.x] += sh[threadIdx.x + s];
        __syncthreads();
    }
    float r = sh[0];
    __syncthreads();
    return r;
}

// ---------------- kernel 0: setup ----------------
__global__ void setup_kernel(const unsigned char* __restrict__ mask) {
    if (threadIdx.x == 0) {
        int nk = 0;
        for (int b = 0; b < BATCH; b++) {
            int mb = mask[b] ? 1 : 0;
            g_maskb[b] = mb;
            if (!mb) g_keep[nk++] = b;
        }
        g_ntok = nk * SEQ;
        g_fill = mask[0] ? 1 : 0;   // quirky fill fires iff batch 0 is masked
    }
}

// ---------------- grouped GEMM (f32x2 packed) ----------------
// mode 0: A = gathered input rows (slot -> token), B = W1[e], out = gelu(.)+b1 -> g_h1
// mode 1: A = g_h1 rows (contiguous by sorted pos), B = W2[e], out = (.)+b2 scattered to d_out
// mode 2: A = token rows, B = w_gate (ldb=64), out = g_logits (routing)
__global__ void __launch_bounds__(256)
gemm_kernel(const float* __restrict__ inp,
            const float* __restrict__ W,
            const float* __restrict__ bias,
            float* __restrict__ out,
            int mode)
{
    __shared__ float As[TK][TM + 4];
    __shared__ float Bs[TK][TN + 4];

    int ntok = g_ntok;
    int e = 0, seg, cnt;
    if (mode == 2) {
        seg = blockIdx.x * TM;
        if (seg >= ntok) return;
        cnt = min(TM, ntok - seg);
    } else {
        if ((int)blockIdx.x >= g_ntiles) return;
        int3 T = g_tiles[blockIdx.x];
        e = T.x; seg = T.y; cnt = T.z;
    }
    int c0  = blockIdx.y * TN;
    int tid = threadIdx.x;
    int tx  = tid & 15, ty = tid >> 4;
    int lr  = tid >> 1, lh = tid & 1;

    const float4* arow = nullptr;
    if (lr < cnt) {
        if (mode == 0) {
            int slot = g_sorted[seg + lr];
            int tok  = slot;  if (tok >= ntok) tok -= ntok;   // gather = j % n
            int gb   = g_keep[tok >> 9];
            arow = reinterpret_cast<const float4*>(inp + ((size_t)gb * SEQ + (tok & 511)) * D_);
        } else if (mode == 1) {
            arow = reinterpret_cast<const float4*>(g_h1 + (size_t)(seg + lr) * D_);
        } else {
            int tok = seg + lr;
            int gb  = g_keep[tok >> 9];
            arow = reinterpret_cast<const float4*>(inp + ((size_t)gb * SEQ + (tok & 511)) * D_);
        }
    }
    const float* Wb = (mode == 2) ? W : (W + (size_t)e * D_ * D_);
    int ldb = (mode == 2) ? E_ : D_;

    unsigned long long acc[4][4];
#pragma unroll
    for (int i = 0; i < 4; i++)
#pragma unroll
        for (int j = 0; j < 4; j++) acc[i][j] = 0ULL;

    for (int k0 = 0; k0 < D_; k0 += TK) {
        float4 v = make_float4(0.f, 0.f, 0.f, 0.f);
        if (arow) v = __ldg(&arow[(k0 >> 2) + lh]);
        As[lh * 4 + 0][lr] = v.x;
        As[lh * 4 + 1][lr] = v.y;
        As[lh * 4 + 2][lr] = v.z;
        As[lh * 4 + 3][lr] = v.w;
#pragma unroll
        for (int u = 0; u < 2; u++) {
            int idx = tid + u * 256;
            int kk = idx >> 6, c = idx & 63;
            Bs[kk][c] = Wb[(size_t)(k0 + kk) * ldb + c0 + c];
        }
        __syncthreads();
#pragma unroll
        for (int kk = 0; kk < TK; kk++) {
            unsigned long long ap[4];
#pragma unroll
            for (int i2 = 0; i2 < 4; i2++)
                ap[i2] = *reinterpret_cast<const unsigned long long*>(&As[kk][ty * 2 + i2 * 32]);
#pragma unroll
            for (int j = 0; j < 4; j++) {
                float bv = Bs[kk][tx + j * 16];
                unsigned long long bp;
                asm("mov.b64 %0, {%1, %1};" : "=l"(bp) : "f"(bv));
#pragma unroll
                for (int i2 = 0; i2 < 4; i2++) fma_f32x2(acc[i2][j], ap[i2], bp);
            }
        }
        __syncthreads();
    }

    // epilogue
#pragma unroll
    for (int i2 = 0; i2 < 4; i2++) {
#pragma unroll
        for (int j = 0; j < 4; j++) {
            unsigned long long av = acc[i2][j];
            float2 r = *reinterpret_cast<float2*>(&av);
            int col = c0 + tx + j * 16;
#pragma unroll
            for (int hh = 0; hh < 2; hh++) {
                int row = ty * 2 + i2 * 32 + hh;
                if (row >= cnt) continue;
                float val = hh ? r.y : r.x;
                if (mode == 0) {
                    val += bias[e * D_ + col];
                    val = gelu_exact(val);
                    g_h1[(size_t)(seg + row) * D_ + col] = val;
                } else if (mode == 1) {
                    val += bias[e * D_ + col];
                    int slot = g_sorted[seg + row];
                    int t = slot >> 1, kq = slot & 1;
                    int gb = g_keep[t >> 9];
                    size_t off = ((((size_t)gb * SEQ + (t & 511)) * 2) + kq) * D_ + col;
                    out[off] = val;
                } else {
                    g_logits[(size_t)(seg + row) * E_ + col] = val;
                }
            }
        }
    }
}

// ---------------- top-2 routing (matches jax top_k tie-break: lowest index) ----------
__global__ void top2_kernel() {
    int t = blockIdx.x;
    if (t >= g_ntok) return;
    __shared__ float sl[E_];
    if ((int)threadIdx.x < E_) sl[threadIdx.x] = g_logits[(size_t)t * E_ + threadIdx.x];
    __syncthreads();
    if (threadIdx.x == 0) {
        int i0 = 0; float v0 = sl[0];
        for (int q = 1; q < E_; q++) if (sl[q] > v0) { v0 = sl[q]; i0 = q; }
        int i1 = -1; float v1 = -3.4e38f;
        for (int q = 0; q < E_; q++) if (q != i0 && sl[q] > v1) { v1 = sl[q]; i1 = q; }
        g_eos[2 * t]     = i0;
        g_eos[2 * t + 1] = i1;
    }
}

// ---------------- bucket slots by expert + build tile list ----------------
__global__ void bucket_kernel() {
    __shared__ int cnt[E_], cur[E_];
    int tid = threadIdx.x;
    if (tid < E_) cnt[tid] = 0;
    __syncthreads();
    int ns = 2 * g_ntok;
    for (int j = tid; j < ns; j += 256) atomicAdd(&cnt[g_eos[j]], 1);
    __syncthreads();
    if (tid == 0) {
        int o = 0, nt = 0;
        for (int q = 0; q < E_; q++) {
            int c = cnt[q];
            cur[q] = o;
            for (int r = 0; r < c; r += TM) {
                g_tiles[nt].x = q;
                g_tiles[nt].y = o + r;
                g_tiles[nt].z = min(TM, c - r);
                nt++;
            }
            o += c;
        }
        g_ntiles = nt;
    }
    __syncthreads();
    for (int j = tid; j < ns; j += 256) {
        int q = g_eos[j];
        int p = atomicAdd(&cur[q], 1);
        g_sorted[p] = j;
    }
}

// ---------------- LN + conf + prob epilogue (reads h back from d_out) ----------------
__global__ void epi_kernel(float* __restrict__ d_out,
                           const float* __restrict__ ln_g, const float* __restrict__ ln_b,
                           const float* __restrict__ Wc,   const float* __restrict__ bc,
                           const float* __restrict__ Wp,   const float* __restrict__ bp,
                           const int*   __restrict__ y_label)
{
    int j = blockIdx.x;
    if (j >= 2 * g_ntok) return;
    int tid = threadIdx.x;
    int e = g_eos[j];
    int t = j >> 1, k = j & 1;
    int gb = g_keep[t >> 9];
    int s  = t & 511;
    size_t hoff = ((((size_t)gb * SEQ + s) * 2) + k) * D_;
    const float* h = d_out + hoff;
    float hv[4];
#pragma unroll
    for (int i = 0; i < 4; i++) hv[i] = h[tid + i * 256];

    __shared__ float red[256];
    float lsum = hv[0] + hv[1] + hv[2] + hv[3];
    float mu = blockReduce(lsum, red) * (1.0f / D_);
    float lvar = 0.f;
#pragma unroll
    for (int i = 0; i < 4; i++) { float d = hv[i] - mu; lvar += d * d; }
    float var = blockReduce(lvar, red) * (1.0f / D_);
    float rstd = rsqrtf(var + 1e-5f);

    float cpart = 0.f, p0 = 0.f, p1 = 0.f;
#pragma unroll
    for (int i = 0; i < 4; i++) {
        int d = tid + i * 256;
        float hn = (hv[i] - mu) * rstd * ln_g[e * D_ + d] + ln_b[e * D_ + d];
        cpart += hn * Wc[e * D_ + d];
        p0 += hv[i] * Wp[d * 2];
        p1 += hv[i] * Wp[d * 2 + 1];
    }
    cpart = blockReduce(cpart, red);
    p0    = blockReduce(p0, red);
    p1    = blockReduce(p1, red);

    if (tid == 0) {
        float conf = 1.0f / (1.0f + expf(-(cpart + bc[e])));
        float l0 = p0 + bp[0], l1 = p1 + bp[1];
        float mx = fmaxf(l0, l1);
        float e0 = expf(l0 - mx), e1 = expf(l1 - mx);
        int y = y_label[gb];
        float pg = ((y == 0) ? e0 : e1) / (e0 + e1);
        size_t cbase = (size_t)BATCH * SEQ * 2 * D_;
        size_t idx = (((size_t)gb * SEQ + s) * 2) + k;
        d_out[cbase + idx] = conf;
        d_out[cbase + (size_t)BATCH * SEQ * 2 + idx] = pg;
    }
}

// ---------------- fill / zero masked batches ----------------
__global__ void fill_kernel(float* __restrict__ d_out, const float* __restrict__ inp) {
    int b = blockIdx.x;
    if (!g_maskb[b]) return;
    int s = blockIdx.y;
    int tid = threadIdx.x;
    const float* src = inp + ((size_t)b * SEQ + s) * D_;
    int fill = g_fill;
    for (int k = 0; k < 2; k++) {
        float* dst = d_out + ((((size_t)b * SEQ + s) * 2) + k) * D_;
        for (int i = tid; i < D_; i += 256) dst[i] = fill ? src[i] : 0.0f;
    }
    if (tid < 2) {
        size_t cbase = (size_t)BATCH * SEQ * 2 * D_;
        size_t idx = (((size_t)b * SEQ + s) * 2) + tid;
        d_out[cbase + idx] = 0.0f;
        d_out[cbase + (size_t)BATCH * SEQ * 2 + idx] = 0.0f;
    }
}

// ---------------- launch ----------------
extern "C" void kernel_launch(void* const* d_in, const int* in_sizes, int n_in,
                              void* d_out, int out_size) {
    const float*         inp     = (const float*)d_in[0];
    const unsigned char* mask    = (const unsigned char*)d_in[1];
    const int*           y_label = (const int*)d_in[2];
    const float*         w_gate  = (const float*)d_in[3];
    const float*         W1      = (const float*)d_in[4];
    const float*         b1      = (const float*)d_in[5];
    const float*         W2      = (const float*)d_in[6];
    const float*         b2      = (const float*)d_in[7];
    const float*         ln_g    = (const float*)d_in[8];
    const float*         ln_b    = (const float*)d_in[9];
    const float*         Wc      = (const float*)d_in[10];
    const float*         bc      = (const float*)d_in[11];
    const float*         Wp      = (const float*)d_in[12];
    const float*         bp      = (const float*)d_in[13];
    float* out = (float*)d_out;

    setup_kernel<<<1, 32>>>(mask);
    // routing logits: (ntok, 64) = X @ w_gate
    gemm_kernel<<<dim3(MAXTOK / TM, 1), 256>>>(inp, w_gate, nullptr, out, 2);
    top2_kernel<<<MAXTOK, 64>>>();
    bucket_kernel<<<1, 256>>>();
    // G1: h1 = gelu(X_gathered @ W1[e] + b1[e])
    gemm_kernel<<<dim3(128, D_ / TN), 256>>>(inp, W1, b1, out, 0);
    // G2: h = h1 @ W2[e] + b2[e] scattered into output tensor
    gemm_kernel<<<dim3(128, D_ / TN), 256>>>(inp, W2, b2, out, 1);
    // LayerNorm + conf + prob heads
    epi_kernel<<<MAXSLOT, 256>>>(out, ln_g, ln_b, Wc, bc, Wp, bp, y_label);
    // masked-batch fill / zeros
    fill_kernel<<<dim3(BATCH, SEQ), 256>>>(out, inp);
}

// round 4
// speedup vs baseline: 2.1320x; 2.1320x over previous
#include <cuda_runtime.h>
#include <cuda_fp16.h>
#include <cstdint>

// ---------------- problem constants ----------------
#define D_      1024
#define E_      64
#define BATCH   8
#define SEQ     512
#define MAXTOK  4096
#define MAXSLOT 8192

// ---------------- device scratch ----------------
__device__ int   g_keep[BATCH];
__device__ int   g_maskb[BATCH];
__device__ int   g_ntok;
__device__ int   g_fill;
__device__ int   g_eos[MAXSLOT];
__device__ int   g_sorted[MAXSLOT];
__device__ int   g_ntiles;
__device__ int3  g_tiles[192];
__device__ float g_logits[MAXTOK * E_];
__device__ float g_h1[(size_t)MAXSLOT * D_];

// ---------------- helpers ----------------
static __device__ __forceinline__ uint32_t smem_u32(const void* p) {
    uint32_t a;
    asm("{ .reg .u64 t; cvta.to.shared.u64 t, %1; cvt.u32.u64 %0, t; }" : "=r"(a) : "l"(p));
    return a;
}
static __device__ __forceinline__ float gelu_exact(float x) {
    return 0.5f * x * (1.0f + erff(x * 0.70710678118654752f));
}
__device__ __forceinline__ void fma_f32x2(unsigned long long& d,
                                          unsigned long long a,
                                          unsigned long long b) {
    asm("fma.rn.f32x2 %0, %1, %2, %0;" : "+l"(d) : "l"(a), "l"(b));
}
// split a pair of floats into fp16 hi + fp16 lo (packed half2 as u32)
static __device__ __forceinline__ void split2(float a, float b, uint32_t& hi, uint32_t& lo) {
    __half ha = __float2half_rn(a), hb = __float2half_rn(b);
    float  ra = a - __half2float(ha), rb = b - __half2float(hb);
    __half2 H = __halves2half2(ha, hb);
    __half2 L = __floats2half2_rn(ra, rb);
    hi = *reinterpret_cast<uint32_t*>(&H);
    lo = *reinterpret_cast<uint32_t*>(&L);
}
static __device__ __forceinline__ void sts128u(uint32_t addr, uint32_t a, uint32_t b,
                                               uint32_t c, uint32_t d) {
    asm volatile("st.shared.v4.b32 [%0], {%1,%2,%3,%4};"
                 :: "r"(addr), "r"(a), "r"(b), "r"(c), "r"(d) : "memory");
}
static __device__ __forceinline__ void ldsm4(uint32_t r[4], uint32_t addr) {
    asm volatile("ldmatrix.sync.aligned.m8n8.x4.shared.b16 {%0,%1,%2,%3}, [%4];"
                 : "=r"(r[0]), "=r"(r[1]), "=r"(r[2]), "=r"(r[3]) : "r"(addr));
}
static __device__ __forceinline__ void ldsm4t(uint32_t r[4], uint32_t addr) {
    asm volatile("ldmatrix.sync.aligned.m8n8.x4.trans.shared.b16 {%0,%1,%2,%3}, [%4];"
                 : "=r"(r[0]), "=r"(r[1]), "=r"(r[2]), "=r"(r[3]) : "r"(addr));
}
static __device__ __forceinline__ void mma16816(float4& c, const uint32_t a[4],
                                                uint32_t b0, uint32_t b1) {
    asm volatile("mma.sync.aligned.m16n8k16.row.col.f32.f16.f16.f32 "
                 "{%0,%1,%2,%3}, {%4,%5,%6,%7}, {%8,%9}, {%0,%1,%2,%3};"
                 : "+f"(c.x), "+f"(c.y), "+f"(c.z), "+f"(c.w)
                 : "r"(a[0]), "r"(a[1]), "r"(a[2]), "r"(a[3]), "r"(b0), "r"(b1));
}

// ================= kernel: setup =================
__global__ void setup_kernel(const unsigned char* __restrict__ mask) {
    if (threadIdx.x == 0) {
        int nk = 0;
        for (int b = 0; b < BATCH; b++) {
            int mb = mask[b] ? 1 : 0;
            g_maskb[b] = mb;
            if (!mb) g_keep[nk++] = b;
        }
        g_ntok = nk * SEQ;
        g_fill = mask[0] ? 1 : 0;
    }
}

// ================= kernel: routing logits (fp32 SIMT, exact) =================
__global__ void __launch_bounds__(256)
logits_kernel(const float* __restrict__ inp, const float* __restrict__ W) {
    __shared__ float As[8][132];
    __shared__ float Bs[8][68];
    int ntok = g_ntok;
    int seg = blockIdx.x * 128;
    if (seg >= ntok) return;
    int cnt = min(128, ntok - seg);
    int tid = threadIdx.x;
    int tx = tid & 15, ty = tid >> 4;
    int lr = tid >> 1, lh = tid & 1;

    const float4* arow = nullptr;
    if (lr < cnt) {
        int tok = seg + lr;
        int gb = g_keep[tok >> 9];
        arow = reinterpret_cast<const float4*>(inp + ((size_t)gb * SEQ + (tok & 511)) * D_);
    }
    unsigned long long acc[4][4];
#pragma unroll
    for (int i = 0; i < 4; i++)
#pragma unroll
        for (int j = 0; j < 4; j++) acc[i][j] = 0ULL;

    for (int k0 = 0; k0 < D_; k0 += 8) {
        float4 v = make_float4(0.f, 0.f, 0.f, 0.f);
        if (arow) v = __ldg(&arow[(k0 >> 2) + lh]);
        As[lh * 4 + 0][lr] = v.x;
        As[lh * 4 + 1][lr] = v.y;
        As[lh * 4 + 2][lr] = v.z;
        As[lh * 4 + 3][lr] = v.w;
#pragma unroll
        for (int u = 0; u < 2; u++) {
            int idx = tid + u * 256;
            int kk = idx >> 6, c = idx & 63;
            Bs[kk][c] = W[(size_t)(k0 + kk) * E_ + c];
        }
        __syncthreads();
#pragma unroll
        for (int kk = 0; kk < 8; kk++) {
            unsigned long long ap[4];
#pragma unroll
            for (int i2 = 0; i2 < 4; i2++)
                ap[i2] = *reinterpret_cast<const unsigned long long*>(&As[kk][ty * 2 + i2 * 32]);
#pragma unroll
            for (int j = 0; j < 4; j++) {
                float bv = Bs[kk][tx + j * 16];
                unsigned long long bp;
                asm("mov.b64 %0, {%1, %1};" : "=l"(bp) : "f"(bv));
#pragma unroll
                for (int i2 = 0; i2 < 4; i2++) fma_f32x2(acc[i2][j], ap[i2], bp);
            }
        }
        __syncthreads();
    }
#pragma unroll
    for (int i2 = 0; i2 < 4; i2++)
#pragma unroll
        for (int j = 0; j < 4; j++) {
            unsigned long long av = acc[i2][j];
            float2 r = *reinterpret_cast<float2*>(&av);
            int col = tx + j * 16;
#pragma unroll
            for (int hh = 0; hh < 2; hh++) {
                int row = ty * 2 + i2 * 32 + hh;
                if (row < cnt)
                    g_logits[(size_t)(seg + row) * E_ + col] = hh ? r.y : r.x;
            }
        }
}

// ================= kernel: top-2 (warp per token) =================
__global__ void __launch_bounds__(256) top2_kernel() {
    int t = blockIdx.x * 8 + (threadIdx.x >> 5);
    if (t >= g_ntok) return;
    int lane = threadIdx.x & 31;
    float v0 = g_logits[(size_t)t * E_ + lane];
    float v1 = g_logits[(size_t)t * E_ + 32 + lane];
    float bv = v0; int bi = lane;
    if (v1 > bv) { bv = v1; bi = lane + 32; }
    float mv = bv; int mi = bi;
#pragma unroll
    for (int o = 16; o; o >>= 1) {
        float ov = __shfl_xor_sync(0xffffffffu, mv, o);
        int oi = __shfl_xor_sync(0xffffffffu, mi, o);
        if (ov > mv || (ov == mv && oi < mi)) { mv = ov; mi = oi; }
    }
    float sv0 = (lane == mi) ? -3.4e38f : v0;
    float sv1 = (lane + 32 == mi) ? -3.4e38f : v1;
    float bv2 = sv0; int bi2 = lane;
    if (sv1 > bv2) { bv2 = sv1; bi2 = lane + 32; }
    float mv2 = bv2; int mi2 = bi2;
#pragma unroll
    for (int o = 16; o; o >>= 1) {
        float ov = __shfl_xor_sync(0xffffffffu, mv2, o);
        int oi = __shfl_xor_sync(0xffffffffu, mi2, o);
        if (ov > mv2 || (ov == mv2 && oi < mi2)) { mv2 = ov; mi2 = oi; }
    }
    if (lane == 0) { g_eos[2 * t] = mi; g_eos[2 * t + 1] = mi2; }
}

// ================= kernel: bucket by expert =================
__global__ void bucket_kernel() {
    __shared__ int cnt[E_], cur[E_];
    int tid = threadIdx.x;
    if (tid < E_) cnt[tid] = 0;
    __syncthreads();
    int ns = 2 * g_ntok;
    for (int j = tid; j < ns; j += 256) atomicAdd(&cnt[g_eos[j]], 1);
    __syncthreads();
    if (tid == 0) {
        int o = 0, nt = 0;
        for (int q = 0; q < E_; q++) {
            int c = cnt[q];
            cur[q] = o;
            for (int r = 0; r < c; r += 128) {
                g_tiles[nt].x = q;
                g_tiles[nt].y = o + r;
                g_tiles[nt].z = min(128, c - r);
                nt++;
            }
            o += c;
        }
        g_ntiles = nt;
    }
    __syncthreads();
    for (int j = tid; j < ns; j += 256) {
        int q = g_eos[j];
        int p = atomicAdd(&cur[q], 1);
        g_sorted[p] = j;
    }
}

// ================= grouped GEMM: mma.sync fp16 3-split =================
// CTA tile 128(M) x 128(N), K chunk 32, double buffered hi/lo half planes.
// mode 0: h1 = gelu(Xgather @ W1[e] + b1[e]) -> g_h1
// mode 1: h  = h1 @ W2[e] + b2[e]            -> scattered to d_out
#define SA_ROW   80          // bytes per A row (40 halves: 32 + 8 pad)
#define SA_PLANE 10240       // 128 rows * 80B
#define SA_STAGE 20480
#define SB_ROW   272         // bytes per B row (136 halves: 128 + 8 pad)
#define SB_PLANE 8704        // 32 rows * 272B
#define SB_STAGE 17408
#define SM_A     0
#define SM_B     40960
#define SM_TOTAL (40960 + 34816)   // 75776 bytes

__global__ void __launch_bounds__(256, 1)
gg_mma(const float* __restrict__ src, const float* __restrict__ W,
       const float* __restrict__ bias, float* __restrict__ out, int mode)
{
    extern __shared__ char smem[];
    if ((int)blockIdx.x >= g_ntiles) return;
    int3 T = g_tiles[blockIdx.x];
    int e = T.x, seg = T.y, cnt = T.z;
    int n0 = blockIdx.y * 128;
    uint32_t sb = smem_u32(smem);
    int tid = threadIdx.x, wid = tid >> 5, lane = tid & 31;
    int wm = (wid & 3) * 32, wn = (wid >> 2) * 64;

    // ---- A source row (gather) ----
    int ar = tid >> 1, ah = tid & 1;     // row 0..127, half 0/1 (16 floats each)
    const float* asrc = nullptr;
    int ntok = g_ntok;
    if (ar < cnt) {
        if (mode == 0) {
            int slot = g_sorted[seg + ar];
            int tok = slot >= ntok ? slot - ntok : slot;   // gather = j % n
            int gb = g_keep[tok >> 9];
            asrc = src + ((size_t)gb * SEQ + (tok & 511)) * D_;
        } else {
            asrc = g_h1 + (size_t)(seg + ar) * D_;
        }
    }
    // ---- B source ----
    int bk = tid >> 3, bn = (tid & 7) * 16;   // k row 0..31, 16 cols
    const float* Wb = W + (size_t)e * D_ * D_ + n0;

    float4 acc[2][8];
#pragma unroll
    for (int i = 0; i < 2; i++)
#pragma unroll
        for (int j = 0; j < 8; j++) acc[i][j] = make_float4(0.f, 0.f, 0.f, 0.f);

    float4 av[4], bv[4];
    // prefetch chunk 0
#pragma unroll
    for (int i = 0; i < 4; i++) {
        av[i] = asrc ? __ldg(reinterpret_cast<const float4*>(asrc + ah * 16) + i)
                     : make_float4(0.f, 0.f, 0.f, 0.f);
        bv[i] = __ldg(reinterpret_cast<const float4*>(Wb + (size_t)bk * D_ + bn) + i);
    }

    for (int c = 0; c < 32; ++c) {
        int st = c & 1;
        // ---- store prefetched chunk into stage st ----
        {
            uint32_t uh[8], ul[8];
#pragma unroll
            for (int i = 0; i < 4; i++) {
                split2(av[i].x, av[i].y, uh[2 * i],     ul[2 * i]);
                split2(av[i].z, av[i].w, uh[2 * i + 1], ul[2 * i + 1]);
            }
            uint32_t aoff = sb + SM_A + st * SA_STAGE + ar * SA_ROW + ah * 32;
            sts128u(aoff,                  uh[0], uh[1], uh[2], uh[3]);
            sts128u(aoff + 16,             uh[4], uh[5], uh[6], uh[7]);
            sts128u(aoff + SA_PLANE,       ul[0], ul[1], ul[2], ul[3]);
            sts128u(aoff + SA_PLANE + 16,  ul[4], ul[5], ul[6], ul[7]);
#pragma unroll
            for (int i = 0; i < 4; i++) {
                split2(bv[i].x, bv[i].y, uh[2 * i],     ul[2 * i]);
                split2(bv[i].z, bv[i].w, uh[2 * i + 1], ul[2 * i + 1]);
            }
            uint32_t boff = sb + SM_B + st * SB_STAGE + bk * SB_ROW + bn * 2;
            sts128u(boff,                  uh[0], uh[1], uh[2], uh[3]);
            sts128u(boff + 16,             uh[4], uh[5], uh[6], uh[7]);
            sts128u(boff + SB_PLANE,       ul[0], ul[1], ul[2], ul[3]);
            sts128u(boff + SB_PLANE + 16,  ul[4], ul[5], ul[6], ul[7]);
        }
        __syncthreads();
        // ---- prefetch chunk c+1 (overlaps with mma below) ----
        if (c < 31) {
            int k0 = (c + 1) * 32;
#pragma unroll
            for (int i = 0; i < 4; i++) {
                av[i] = asrc ? __ldg(reinterpret_cast<const float4*>(asrc + k0 + ah * 16) + i)
                             : make_float4(0.f, 0.f, 0.f, 0.f);
                bv[i] = __ldg(reinterpret_cast<const float4*>(Wb + (size_t)(k0 + bk) * D_ + bn) + i);
            }
        }
        // ---- compute from stage st ----
        uint32_t Ab = sb + SM_A + st * SA_STAGE;
        uint32_t Bb = sb + SM_B + st * SB_STAGE;
#pragma unroll
        for (int ks = 0; ks < 2; ++ks) {
            uint32_t ahi[2][4], alo[2][4];
#pragma unroll
            for (int mt = 0; mt < 2; mt++) {
                uint32_t ad = Ab + (wm + mt * 16 + (lane & 15)) * SA_ROW
                            + ks * 32 + ((lane >> 4) << 4);
                ldsm4(ahi[mt], ad);
                ldsm4(alo[mt], ad + SA_PLANE);
            }
#pragma unroll
            for (int nb = 0; nb < 4; nb++) {
                uint32_t bd = Bb + (ks * 16 + (lane & 7) + ((lane >> 3) & 1) * 8) * SB_ROW
                            + (wn + nb * 16 + ((lane >> 4) << 3)) * 2;
                uint32_t bh[4], bl[4];
                ldsm4t(bh, bd);
                ldsm4t(bl, bd + SB_PLANE);
#pragma unroll
                for (int mt = 0; mt < 2; mt++) {
                    mma16816(acc[mt][nb * 2 + 0], ahi[mt], bh[0], bh[1]);
                    mma16816(acc[mt][nb * 2 + 0], ahi[mt], bl[0], bl[1]);
                    mma16816(acc[mt][nb * 2 + 0], alo[mt], bh[0], bh[1]);
                    mma16816(acc[mt][nb * 2 + 1], ahi[mt], bh[2], bh[3]);
                    mma16816(acc[mt][nb * 2 + 1], ahi[mt], bl[2], bl[3]);
                    mma16816(acc[mt][nb * 2 + 1], alo[mt], bh[2], bh[3]);
                }
            }
        }
        __syncthreads();
    }

    // ---- epilogue: write fragments directly ----
    int gr = lane >> 2, gc = (lane & 3) * 2;
    const float* bias_e = bias + (size_t)e * D_;
    float* dptr = (mode == 0) ? g_h1 : out;
    size_t dsto[2][2];
    bool actv[2][2];
#pragma unroll
    for (int mt = 0; mt < 2; mt++)
#pragma unroll
        for (int h = 0; h < 2; h++) {
            int r = wm + mt * 16 + gr + h * 8;
            bool a = r < cnt;
            actv[mt][h] = a;
            size_t o = 0;
            if (a) {
                if (mode == 0) {
                    o = (size_t)(seg + r) * D_;
                } else {
                    int slot = g_sorted[seg + r];
                    int t = slot >> 1, kq = slot & 1;
                    int gb = g_keep[t >> 9];
                    o = ((((size_t)gb * SEQ + (t & 511)) * 2) + kq) * D_;
                }
            }
            dsto[mt][h] = o;
        }
#pragma unroll
    for (int nb = 0; nb < 4; nb++)
#pragma unroll
        for (int h8 = 0; h8 < 2; h8++) {
            int colg = n0 + wn + nb * 16 + h8 * 8 + gc;
            float2 b2 = *reinterpret_cast<const float2*>(bias_e + colg);
#pragma unroll
            for (int mt = 0; mt < 2; mt++) {
                float4 cc = acc[mt][nb * 2 + h8];
                float2 v0 = make_float2(cc.x + b2.x, cc.y + b2.y);
                float2 v1 = make_float2(cc.z + b2.x, cc.w + b2.y);
                if (mode == 0) {
                    v0.x = gelu_exact(v0.x); v0.y = gelu_exact(v0.y);
                    v1.x = gelu_exact(v1.x); v1.y = gelu_exact(v1.y);
                }
                if (actv[mt][0]) *reinterpret_cast<float2*>(dptr + dsto[mt][0] + colg) = v0;
                if (actv[mt][1]) *reinterpret_cast<float2*>(dptr + dsto[mt][1] + colg) = v1;
            }
        }
}

// ================= kernel: LN + conf + prob (warp per slot) =================
__global__ void __launch_bounds__(256)
epi_kernel(float* __restrict__ d_out,
           const float* __restrict__ ln_g, const float* __restrict__ ln_b,
           const float* __restrict__ Wc,   const float* __restrict__ bc,
           const float* __restrict__ Wp,   const float* __restrict__ bp,
           const int*   __restrict__ y_label)
{
    int j = blockIdx.x * 8 + (threadIdx.x >> 5);
    if (j >= 2 * g_ntok) return;
    int lane = threadIdx.x & 31;
    int e = g_eos[j];
    int t = j >> 1, k = j & 1;
    int gb = g_keep[t >> 9], s = t & 511;
    const float* h = d_out + ((((size_t)gb * SEQ + s) * 2) + k) * D_;
    float4 hv[8];
#pragma unroll
    for (int i = 0; i < 8; ++i) hv[i] = __ldg(reinterpret_cast<const float4*>(h) + lane + i * 32);

    float sum = 0.f;
#pragma unroll
    for (int i = 0; i < 8; ++i) sum += hv[i].x + hv[i].y + hv[i].z + hv[i].w;
#pragma unroll
    for (int o = 16; o; o >>= 1) sum += __shfl_xor_sync(0xffffffffu, sum, o);
    float mu = sum * (1.0f / D_);

    float var = 0.f;
#pragma unroll
    for (int i = 0; i < 8; ++i) {
        float a = hv[i].x - mu, b = hv[i].y - mu, c2 = hv[i].z - mu, d = hv[i].w - mu;
        var += a * a + b * b + c2 * c2 + d * d;
    }
#pragma unroll
    for (int o = 16; o; o >>= 1) var += __shfl_xor_sync(0xffffffffu, var, o);
    float rstd = rsqrtf(var * (1.0f / D_) + 1e-5f);

    float cpart = 0.f, p0 = 0.f, p1 = 0.f;
#pragma unroll
    for (int i = 0; i < 8; ++i) {
        int q = lane + i * 32;
        float4 g4 = __ldg(reinterpret_cast<const float4*>(ln_g + (size_t)e * D_) + q);
        float4 b4 = __ldg(reinterpret_cast<const float4*>(ln_b + (size_t)e * D_) + q);
        float4 w4 = __ldg(reinterpret_cast<const float4*>(Wc + (size_t)e * D_) + q);
        float4 pa = __ldg(reinterpret_cast<const float4*>(Wp) + q * 2);
        float4 pb = __ldg(reinterpret_cast<const float4*>(Wp) + q * 2 + 1);
        float hnx = (hv[i].x - mu) * rstd * g4.x + b4.x;
        float hny = (hv[i].y - mu) * rstd * g4.y + b4.y;
        float hnz = (hv[i].z - mu) * rstd * g4.z + b4.z;
        float hnw = (hv[i].w - mu) * rstd * g4.w + b4.w;
        cpart += hnx * w4.x + hny * w4.y + hnz * w4.z + hnw * w4.w;
        p0 += hv[i].x * pa.x + hv[i].y * pa.z + hv[i].z * pb.x + hv[i].w * pb.z;
        p1 += hv[i].x * pa.y + hv[i].y * pa.w + hv[i].z * pb.y + hv[i].w * pb.w;
    }
#pragma unroll
    for (int o = 16; o; o >>= 1) {
        cpart += __shfl_xor_sync(0xffffffffu, cpart, o);
        p0    += __shfl_xor_sync(0xffffffffu, p0, o);
        p1    += __shfl_xor_sync(0xffffffffu, p1, o);
    }
    if (lane == 0) {
        float conf = 1.0f / (1.0f + expf(-(cpart + bc[e])));
        float l0 = p0 + bp[0], l1 = p1 + bp[1];
        float mx = fmaxf(l0, l1);
        float e0 = expf(l0 - mx), e1 = expf(l1 - mx);
        int y = y_label[gb];
        float pg = ((y == 0) ? e0 : e1) / (e0 + e1);
        size_t cbase = (size_t)BATCH * SEQ * 2 * D_;
        size_t idx = (((size_t)gb * SEQ + s) * 2) + k;
        d_out[cbase + idx] = conf;
        d_out[cbase + (size_t)BATCH * SEQ * 2 + idx] = pg;
    }
}

// ================= kernel: masked-batch fill =================
__global__ void fill_kernel(float* __restrict__ d_out, const float* __restrict__ inp) {
    int b = blockIdx.x;
    if (!g_maskb[b]) return;
    int s = blockIdx.y;
    int tid = threadIdx.x;
    const float* src = inp + ((size_t)b * SEQ + s) * D_;
    int fill = g_fill;
    for (int k = 0; k < 2; k++) {
        float* dst = d_out + ((((size_t)b * SEQ + s) * 2) + k) * D_;
        for (int i = tid; i < D_; i += 256) dst[i] = fill ? src[i] : 0.0f;
    }
    if (tid < 2) {
        size_t cbase = (size_t)BATCH * SEQ * 2 * D_;
        size_t idx = (((size_t)b * SEQ + s) * 2) + tid;
        d_out[cbase + idx] = 0.0f;
        d_out[cbase + (size_t)BATCH * SEQ * 2 + idx] = 0.0f;
    }
}

// ================= host launch =================
extern "C" void kernel_launch(void* const* d_in, const int* in_sizes, int n_in,
                              void* d_out, int out_size) {
    const float*         inp     = (const float*)d_in[0];
    const unsigned char* mask    = (const unsigned char*)d_in[1];
    const int*           y_label = (const int*)d_in[2];
    const float*         w_gate  = (const float*)d_in[3];
    const float*         W1      = (const float*)d_in[4];
    const float*         b1      = (const float*)d_in[5];
    const float*         W2      = (const float*)d_in[6];
    const float*         b2      = (const float*)d_in[7];
    const float*         ln_g    = (const float*)d_in[8];
    const float*         ln_b    = (const float*)d_in[9];
    const float*         Wc      = (const float*)d_in[10];
    const float*         bc      = (const float*)d_in[11];
    const float*         Wp      = (const float*)d_in[12];
    const float*         bp      = (const float*)d_in[13];
    float* out = (float*)d_out;

    cudaFuncSetAttribute(gg_mma, cudaFuncAttributeMaxDynamicSharedMemorySize, SM_TOTAL);

    setup_kernel<<<1, 32>>>(mask);
    logits_kernel<<<32, 256>>>(inp, w_gate);
    top2_kernel<<<512, 256>>>();
    bucket_kernel<<<1, 256>>>();
    gg_mma<<<dim3(128, 8), 256, SM_TOTAL>>>(inp, W1, b1, out, 0);
    gg_mma<<<dim3(128, 8), 256, SM_TOTAL>>>(nullptr, W2, b2, out, 1);
    epi_kernel<<<1024, 256>>>(out, ln_g, ln_b, Wc, bc, Wp, bp, y_label);
    fill_kernel<<<dim3(BATCH, SEQ), 256>>>(out, inp);
}